// round 16
// baseline (speedup 1.0000x reference)
#include <cuda_runtime.h>
#include <cuda_fp16.h>
#include <cstdint>

// ============================================================================
// Problem sizes
// ============================================================================
static constexpr int NVOX  = 65536;
static constexpr int CIN   = 64;
static constexpr int CH    = 64;
static constexpr int COUT3 = 16;
static constexpr int KOFF  = 27;
static constexpr int NBLK  = 256;             // rows per fill block
static constexpr int NROWB = NVOX / NBLK;     // 256 blocks
static constexpr int PMAX  = KOFF * NVOX;     // fixed per-k segments of NVOX
static constexpr int TILE  = 128;             // pair rows per phase-A tile
static constexpr int TMAXT = KOFF * (NVOX / TILE);
static constexpr int NWARP = NBLK / 32;       // 8

// ============================================================================
// Device scratch (no dynamic allocation allowed)
// ============================================================================
__device__ __half g_xh[NVOX * CIN];
__device__ __half g_h1[NVOX * CH];
__device__ __half g_h2[NVOX * CH];
__device__ __half g_W1f[KOFF * CH * CIN];
__device__ __half g_W2f[KOFF * CH * CH];
__device__ __half g_W3f[KOFF * COUT3 * CH];

__device__ int    g_inlist[PMAX];                   // input row per pair
__device__ __half g_partial[(size_t)PMAX * 64];     // pair partial rows
__device__ int    g_rowpairs[NVOX * KOFF];          // per-row pair ids
__device__ int    g_rcnt[NVOX];
__device__ int    g_kcnt[KOFF];                     // pairs per offset
__device__ int2   g_tiles[TMAXT];                   // {start, k | cnt<<8}
__device__ int    g_ntiles[1];

// ============================================================================
// PTX helpers
// ============================================================================
__device__ __forceinline__ uint32_t smem_to_u32(const void* smem_ptr) {
    uint32_t addr;
    asm("{ .reg .u64 tmp; cvta.to.shared.u64 tmp, %1; cvt.u32.u64 %0, tmp; }"
        : "=r"(addr) : "l"(smem_ptr));
    return addr;
}
__device__ __forceinline__ void cp_async16(uint32_t dst, const void* src) {
    asm volatile("cp.async.cg.shared.global [%0], [%1], 16;"
                 :: "r"(dst), "l"(src));
}
__device__ __forceinline__ void cp_commit() {
    asm volatile("cp.async.commit_group;");
}
template <int N>
__device__ __forceinline__ void cp_wait() {
    asm volatile("cp.async.wait_group %0;" :: "n"(N));
}
__device__ __forceinline__ void ldmatrix_x4(uint32_t* a, uint32_t addr) {
    asm volatile("ldmatrix.sync.aligned.m8n8.x4.shared.b16 {%0,%1,%2,%3}, [%4];"
                 : "=r"(a[0]), "=r"(a[1]), "=r"(a[2]), "=r"(a[3]) : "r"(addr));
}
__device__ __forceinline__ void mma16816(float* c, const uint32_t* a,
                                         const uint32_t* b) {
    asm volatile(
        "mma.sync.aligned.m16n8k16.row.col.f32.f16.f16.f32 "
        "{%0,%1,%2,%3}, {%4,%5,%6,%7}, {%8,%9}, {%0,%1,%2,%3};"
        : "+f"(c[0]), "+f"(c[1]), "+f"(c[2]), "+f"(c[3])
        : "r"(a[0]), "r"(a[1]), "r"(a[2]), "r"(a[3]), "r"(b[0]), "r"(b[1]));
}

// ============================================================================
// Pair-list construction: ONE pass over nidx. Pairs for offset k land in the
// fixed segment [k*NVOX, ...) via block-aggregated atomicAdd. Placement order
// is nondeterministic but output-invariant (partial[p] depends only on
// (inlist[p], k); phaseB sums in fixed slot order).
// ============================================================================
__global__ void __launch_bounds__(NBLK)
k_fill(const int* __restrict__ nidx, int* __restrict__ kcnt,
       int* __restrict__ inlist, int* __restrict__ rowpairs,
       int* __restrict__ rcnt) {
    __shared__ int wpre[KOFF][NWARP];
    __shared__ int kbase[KOFF];
    const int t = threadIdx.x, b = blockIdx.x;
    const int w = t >> 5, lane = t & 31;
    const int row = b * NBLK + t;
    const int* ip = nidx + (size_t)row * KOFF;
    unsigned m = 0;
    #pragma unroll
    for (int k = 0; k < KOFF; k++)
        m |= (unsigned)(ip[k] >= 0) << k;
    #pragma unroll
    for (int k = 0; k < KOFF; k++) {
        unsigned bal = __ballot_sync(0xFFFFFFFFu, (m >> k) & 1u);
        if (lane == 0) wpre[k][w] = __popc(bal);
    }
    __syncthreads();
    if (t < KOFF) {
        int run = 0;
        #pragma unroll
        for (int g = 0; g < NWARP; g++) {
            int c = wpre[t][g];
            wpre[t][g] = run;
            run += c;
        }
        kbase[t] = atomicAdd(&kcnt[t], run);
    }
    __syncthreads();
    int slot = 0;
    const unsigned lt = (lane == 0) ? 0u : (0xFFFFFFFFu >> (32 - lane));
    #pragma unroll
    for (int k = 0; k < KOFF; k++) {
        const unsigned v = (m >> k) & 1u;
        const unsigned bal = __ballot_sync(0xFFFFFFFFu, v);
        if (v) {
            int p = k * NVOX + kbase[k] + wpre[k][w] + __popc(bal & lt);
            inlist[p] = ip[k];
            rowpairs[(size_t)row * KOFF + slot] = p;
            slot++;
        }
    }
    rcnt[row] = slot;
}

__global__ void k_tiles(const int* __restrict__ kcnt, int2* __restrict__ tiles,
                        int* __restrict__ ntiles) {
    __shared__ int tc[KOFF], tb[KOFF];
    const int t = threadIdx.x;
    if (t < KOFF) tc[t] = (kcnt[t] + TILE - 1) / TILE;
    __syncthreads();
    if (t == 0) {
        int run = 0;
        for (int k = 0; k < KOFF; k++) { tb[k] = run; run += tc[k]; }
        *ntiles = run;
    }
    __syncthreads();
    if (t < KOFF) {
        const int cnt = kcnt[t];
        for (int j = 0; j < tc[t]; j++)
            tiles[tb[t] + j] = make_int2(t * NVOX + j * TILE,
                                         t | (min(TILE, cnt - j * TILE) << 8));
    }
}

// ============================================================================
// Phase A (depth-2 cp.async pipeline, 256 threads, 8 warps x m16, TILE=128,
// contiguous tile ranges; B staged to SMEM only on k-change and held in
// REGISTERS across tiles of the same k):
//   per tile (one k): partial[p,:] = feat[inlist[p],:] @ W[k]
// ============================================================================
template <int COUT>
__global__ void __launch_bounds__(256, 2)
phaseA(const __half* __restrict__ feat, const __half* __restrict__ Wf,
       const int* __restrict__ inlist, const int2* __restrict__ tiles,
       const int* __restrict__ ntiles_p, __half* __restrict__ partial)
{
    constexpr int NO       = COUT / 8;
    constexpr int B_BYTES  = COUT * 128;
    constexpr int A_BYTES  = TILE * 128;     // 16384
    extern __shared__ char smem[];
    const uint32_t smem_base = smem_to_u32(smem);
    const uint32_t bRegion   = smem_base + 2 * A_BYTES;
    const int tid  = threadIdx.x;
    const int wid  = tid >> 5;               // 0..7
    const int lane = tid & 31;
    const int nt   = *ntiles_p;
    const int m0   = wid * 16;               // 8 warps x m16 = 128 rows
    const int G    = gridDim.x;

    // contiguous balanced range [t0, te)
    const int per = nt / G;
    const int rem = nt - per * G;
    const int t0  = blockIdx.x * per + min(blockIdx.x, rem);
    const int te  = t0 + per + (blockIdx.x < rem ? 1 : 0);

    int kprev = -1;          // k of previously staged tile (uniform)
    int bsel  = 0;           // current B slot (uniform)
    int bslot[2];            // B slot used by tile staged into A-slot parity

    // stage tile t into A slot abuf; B copied only when k changes.
    // ALWAYS commits so group counting stays uniform for the tail.
    auto stage = [&](int t, int abuf) {
        if (t < te) {
            const int2 d = tiles[t];
            const int start = d.x;
            const int k     = d.y & 31;
            const int cnt   = d.y >> 8;
            const bool newk = (k != kprev);
            kprev = k;
            if (newk) bsel ^= 1;
            bslot[abuf] = bsel;
            if (newk) {
                const char* bs = (const char*)Wf + (size_t)k * B_BYTES;
                const uint32_t bd = bRegion + bsel * B_BYTES;
                #pragma unroll
                for (int j = tid; j < B_BYTES / 16; j += 256)
                    cp_async16(bd + j * 16, bs + (size_t)j * 16);
            }
            // coalesced gather: row r = c*32 + tid/8, chunk = tid%8
            const uint32_t base = smem_base + abuf * A_BYTES;
            const int ch = tid & 7;
            #pragma unroll
            for (int c = 0; c < 4; c++) {
                const int r = c * 32 + (tid >> 3);
                if (r < cnt) {
                    int in_row = inlist[start + r];
                    const char* src = (const char*)(feat + (size_t)in_row * 64)
                                      + ch * 16;
                    cp_async16(base + r * 128 + ((uint32_t)(ch * 16)
                               ^ ((uint32_t)(r & 7) * 16)), src);
                }
            }
        }
        cp_commit();
    };

    stage(t0, 0);

    uint32_t bfrag[4][NO][2];    // B fragments held across same-k tiles
    int kreg = -1;

    int si = 0;
    for (int t = t0; t < te; t++, si++) {
        stage(t + 1, (si + 1) & 1);
        cp_wait<1>();                 // tile t's group is now complete
        __syncthreads();

        const int2 d = tiles[t];
        const int start = d.x;
        const int cnt   = d.y >> 8;
        const int kt    = d.y & 31;
        const int abuf  = si & 1;
        const uint32_t aBase = smem_base + abuf * A_BYTES;

        if (kt != kreg) {             // reload B fragments (once per k)
            kreg = kt;
            const uint32_t bBase = bRegion + bslot[abuf] * B_BYTES;
            #pragma unroll
            for (int ko = 0; ko < 4; ko++)
                #pragma unroll
                for (int no = 0; no < NO; no++)
                    asm volatile("ld.shared.v2.b32 {%0,%1}, [%2];"
                                 : "=r"(bfrag[ko][no][0]),
                                   "=r"(bfrag[ko][no][1])
                                 : "r"(bBase + ((ko * NO + no) * 32 + lane) * 8));
        }

        float acc[NO][4];
        #pragma unroll
        for (int no = 0; no < NO; no++)
            #pragma unroll
            for (int r = 0; r < 4; r++)
                acc[no][r] = 0.f;

        #pragma unroll
        for (int ko = 0; ko < 4; ko++) {
            uint32_t afrag[4];
            const int ch = ko * 2 + (lane >> 4);
            const int r  = m0 + (lane & 15);
            ldmatrix_x4(afrag,
                aBase + r * 128 + (((uint32_t)ch ^ (uint32_t)(r & 7)) * 16));
            #pragma unroll
            for (int no = 0; no < NO; no++)
                mma16816(acc[no], afrag, bfrag[ko][no]);
        }

        // ---- direct global stores, tail-guarded ----
        {
            const int lr = m0 + (lane >> 2);
            #pragma unroll
            for (int no = 0; no < NO; no++) {
                const int c0 = no * 8 + (lane & 3) * 2;
                if (lr < cnt)
                    *(__half2*)(partial + (size_t)(start + lr) * COUT + c0) =
                        __floats2half2_rn(acc[no][0], acc[no][1]);
                if (lr + 8 < cnt)
                    *(__half2*)(partial + (size_t)(start + lr + 8) * COUT + c0) =
                        __floats2half2_rn(acc[no][2], acc[no][3]);
            }
        }
        __syncthreads();   // all A/B reads done before stage() reuses slots
    }
}

// ============================================================================
// Phase B (MLP-pipelined): out[row,:] = act( sum_j partial[rp[j],:] + bias )
// First UNR pair loads are issued unconditionally (addresses clamped to
// rp[0], always valid since the center offset is self-valid => cnt >= 1);
// accumulation is predicated in ascending j order => bit-identical sums.
// ============================================================================
template <int COUT, bool RELU, typename OUT_T>
__global__ void __launch_bounds__(256)
phaseB(const __half* __restrict__ partial, const int* __restrict__ rowpairs,
       const int* __restrict__ rcnt, const float* __restrict__ bias,
       OUT_T* __restrict__ out)
{
    constexpr int TPR = COUT / 16;
    constexpr int UNR = 6;
    const int gid = blockIdx.x * 256 + threadIdx.x;
    const int row = gid / TPR;
    const int q   = gid % TPR;

    float acc[16];
    #pragma unroll
    for (int i = 0; i < 16; i++) acc[i] = bias[q * 16 + i];

    const int cnt = rcnt[row];
    const int* rp = rowpairs + (size_t)row * KOFF;

    int pj[UNR];
    #pragma unroll
    for (int j = 0; j < UNR; j++)
        pj[j] = rp[j < cnt ? j : 0];

    #pragma unroll
    for (int j = 0; j < UNR; j++) {
        const uint4* pr = (const uint4*)(partial + (size_t)pj[j] * COUT + q * 16);
        uint4 u0 = pr[0], u1 = pr[1];
        if (j < cnt) {
            const uint32_t* u = (const uint32_t*)&u0;
            #pragma unroll
            for (int h = 0; h < 4; h++) {
                float2 f = __half22float2(*(const __half2*)&u[h]);
                acc[h * 2]     += f.x;
                acc[h * 2 + 1] += f.y;
            }
            const uint32_t* v = (const uint32_t*)&u1;
            #pragma unroll
            for (int h = 0; h < 4; h++) {
                float2 f = __half22float2(*(const __half2*)&v[h]);
                acc[8 + h * 2]     += f.x;
                acc[8 + h * 2 + 1] += f.y;
            }
        }
    }
    for (int j = UNR; j < cnt; j++) {       // rare tail (cnt > 6)
        const int p = rp[j];
        const uint4* pr = (const uint4*)(partial + (size_t)p * COUT + q * 16);
        uint4 u0 = pr[0], u1 = pr[1];
        const uint32_t* u = (const uint32_t*)&u0;
        #pragma unroll
        for (int h = 0; h < 4; h++) {
            float2 f = __half22float2(*(const __half2*)&u[h]);
            acc[h * 2]     += f.x;
            acc[h * 2 + 1] += f.y;
        }
        const uint32_t* v = (const uint32_t*)&u1;
        #pragma unroll
        for (int h = 0; h < 4; h++) {
            float2 f = __half22float2(*(const __half2*)&v[h]);
            acc[8 + h * 2]     += f.x;
            acc[8 + h * 2 + 1] += f.y;
        }
    }

    if (RELU) {
        #pragma unroll
        for (int i = 0; i < 16; i++) acc[i] = fmaxf(acc[i], 0.f);
    }
    if constexpr (sizeof(OUT_T) == 2) {
        __half2 hs[8];
        #pragma unroll
        for (int i = 0; i < 8; i++)
            hs[i] = __floats2half2_rn(acc[2 * i], acc[2 * i + 1]);
        uint4* dst = (uint4*)((__half*)out + (size_t)row * COUT + q * 16);
        dst[0] = *(uint4*)&hs[0];
        dst[1] = *(uint4*)&hs[4];
    } else {
        float4* dst = (float4*)((float*)out + (size_t)row * COUT + q * 16);
        #pragma unroll
        for (int i = 0; i < 4; i++)
            dst[i] = make_float4(acc[4 * i], acc[4 * i + 1],
                                 acc[4 * i + 2], acc[4 * i + 3]);
    }
}

// ============================================================================
// Fused prologue: x -> fp16, and W1/W2/W3 -> mma B-fragment order
// ============================================================================
__device__ __forceinline__ void prep_b_elem(const float* __restrict__ W,
                                            __half* __restrict__ Bf,
                                            int Cout, int i) {
    int NOv  = Cout / 8;
    int lane = i & 31;
    int g    = i >> 5;
    int no   = g % NOv;
    int ko   = (g / NOv) % 4;
    int k    = g / (NOv * 4);
    int n    = no * 8 + (lane >> 2);
    int kk0  = ko * 16 + (lane & 3) * 2;
    const float* Wk = W + (size_t)k * 64 * Cout;
    __half h0 = __float2half_rn(Wk[(kk0 + 0) * Cout + n]);
    __half h1 = __float2half_rn(Wk[(kk0 + 1) * Cout + n]);
    __half h2 = __float2half_rn(Wk[(kk0 + 8) * Cout + n]);
    __half h3 = __float2half_rn(Wk[(kk0 + 9) * Cout + n]);
    uint2 v;
    v.x = (uint32_t)__half_as_ushort(h0) | ((uint32_t)__half_as_ushort(h1) << 16);
    v.y = (uint32_t)__half_as_ushort(h2) | ((uint32_t)__half_as_ushort(h3) << 16);
    ((uint2*)Bf)[i] = v;
}

static constexpr int PREP_NP  = NVOX * CIN / 2;
static constexpr int PREP_T12 = KOFF * 4 * 8 * 32;
static constexpr int PREP_T3  = KOFF * 4 * 2 * 32;
static constexpr int PREP_TOT = PREP_NP + 2 * PREP_T12 + PREP_T3;

__global__ void k_prep(const float* __restrict__ x, __half* __restrict__ xh,
                       const float* __restrict__ W1, __half* __restrict__ w1f,
                       const float* __restrict__ W2, __half* __restrict__ w2f,
                       const float* __restrict__ W3, __half* __restrict__ w3f) {
    int i = blockIdx.x * blockDim.x + threadIdx.x;
    if (i < PREP_NP) {
        float2 v = ((const float2*)x)[i];
        ((__half2*)xh)[i] = __floats2half2_rn(v.x, v.y);
    } else if (i < PREP_NP + PREP_T12) {
        prep_b_elem(W1, w1f, 64, i - PREP_NP);
    } else if (i < PREP_NP + 2 * PREP_T12) {
        prep_b_elem(W2, w2f, 64, i - PREP_NP - PREP_T12);
    } else if (i < PREP_TOT) {
        prep_b_elem(W3, w3f, 16, i - PREP_NP - 2 * PREP_T12);
    }
}

// ============================================================================
// kernel_launch
// ============================================================================
extern "C" void kernel_launch(void* const* d_in, const int* in_sizes, int n_in,
                              void* d_out, int out_size) {
    const float* x    = (const float*)d_in[0];
    const int*   nidx = (const int*)  d_in[1];
    const float* W1   = (const float*)d_in[2];
    const float* b1   = (const float*)d_in[3];
    const float* W2   = (const float*)d_in[4];
    const float* b2   = (const float*)d_in[5];
    const float* W3   = (const float*)d_in[6];
    const float* b3   = (const float*)d_in[7];

    __half *xh, *h1, *h2, *w1f, *w2f, *w3f, *part;
    int *inl, *rp, *rc, *kc, *ntl;
    int2* tl;
    cudaGetSymbolAddress((void**)&xh,   g_xh);
    cudaGetSymbolAddress((void**)&h1,   g_h1);
    cudaGetSymbolAddress((void**)&h2,   g_h2);
    cudaGetSymbolAddress((void**)&w1f,  g_W1f);
    cudaGetSymbolAddress((void**)&w2f,  g_W2f);
    cudaGetSymbolAddress((void**)&w3f,  g_W3f);
    cudaGetSymbolAddress((void**)&part, g_partial);
    cudaGetSymbolAddress((void**)&inl,  g_inlist);
    cudaGetSymbolAddress((void**)&rp,   g_rowpairs);
    cudaGetSymbolAddress((void**)&rc,   g_rcnt);
    cudaGetSymbolAddress((void**)&kc,   g_kcnt);
    cudaGetSymbolAddress((void**)&tl,   g_tiles);
    cudaGetSymbolAddress((void**)&ntl,  g_ntiles);

    // ---- fork: pair-list branch (reads only nidx) runs parallel to k_prep ----
    cudaStream_t s1;
    cudaStreamCreateWithFlags(&s1, cudaStreamNonBlocking);
    cudaEvent_t e0, e1;
    cudaEventCreateWithFlags(&e0, cudaEventDisableTiming);
    cudaEventCreateWithFlags(&e1, cudaEventDisableTiming);

    cudaEventRecord(e0, 0);
    cudaStreamWaitEvent(s1, e0, 0);

    k_prep<<<(PREP_TOT + 255) / 256, 256>>>(x, xh, W1, w1f, W2, w2f, W3, w3f);

    cudaMemsetAsync(kc, 0, KOFF * sizeof(int), s1);
    k_fill<<<NROWB, NBLK, 0, s1>>>(nidx, kc, inl, rp, rc);
    k_tiles<<<1, 32, 0, s1>>>(kc, tl, ntl);

    cudaEventRecord(e1, s1);
    cudaStreamWaitEvent(0, e1, 0);

    constexpr int SZA64 = 2 * TILE * 128 + 2 * 64 * 128;  // 49152
    constexpr int SZA16 = 2 * TILE * 128 + 2 * 16 * 128;  // 36864
    constexpr int GA = 296;                               // 2 CTAs/SM
    cudaFuncSetAttribute((const void*)phaseA<64>,
                         cudaFuncAttributeMaxDynamicSharedMemorySize, SZA64);
    cudaFuncSetAttribute((const void*)phaseA<16>,
                         cudaFuncAttributeMaxDynamicSharedMemorySize, SZA16);

    // layer 1
    phaseA<64><<<GA, 256, SZA64>>>(xh, w1f, inl, tl, ntl, part);
    phaseB<64, true, __half><<<NVOX * 4 / 256, 256>>>(part, rp, rc, b1, h1);
    // layer 2
    phaseA<64><<<GA, 256, SZA64>>>(h1, w2f, inl, tl, ntl, part);
    phaseB<64, true, __half><<<NVOX * 4 / 256, 256>>>(part, rp, rc, b2, h2);
    // layer 3
    phaseA<16><<<GA, 256, SZA16>>>(h2, w3f, inl, tl, ntl, part);
    phaseB<16, false, float><<<NVOX / 256, 256>>>(part, rp, rc, b3,
                                                  (float*)d_out);

    cudaEventDestroy(e0);
    cudaEventDestroy(e1);
    cudaStreamDestroy(s1);
}

// round 17
// speedup vs baseline: 1.0275x; 1.0275x over previous
#include <cuda_runtime.h>
#include <cuda_fp16.h>
#include <cstdint>

// ============================================================================
// Problem sizes
// ============================================================================
static constexpr int NVOX  = 65536;
static constexpr int CIN   = 64;
static constexpr int CH    = 64;
static constexpr int COUT3 = 16;
static constexpr int KOFF  = 27;
static constexpr int NBLK  = 256;             // rows per fill block
static constexpr int NROWB = NVOX / NBLK;     // 256 blocks
static constexpr int PMAX  = KOFF * NVOX;     // fixed per-k segments of NVOX
static constexpr int TILE  = 128;             // pair rows per phase-A tile
static constexpr int TMAXT = KOFF * (NVOX / TILE);
static constexpr int NWARP = NBLK / 32;       // 8

// ============================================================================
// Device scratch (no dynamic allocation allowed)
// ============================================================================
__device__ __half g_xh[NVOX * CIN];
__device__ __half g_h1[NVOX * CH];
__device__ __half g_h2[NVOX * CH];
__device__ __half g_W1f[KOFF * CH * CIN];
__device__ __half g_W2f[KOFF * CH * CH];
__device__ __half g_W3f[KOFF * COUT3 * CH];

__device__ int    g_inlist[PMAX];                   // input row per pair
__device__ __half g_partial[(size_t)PMAX * 64];     // pair partial rows
__device__ int    g_rowpairs[NVOX * KOFF];          // per-row pair ids
__device__ int    g_rcnt[NVOX];
__device__ int    g_kcnt[KOFF];                     // pairs per offset
__device__ int2   g_tiles[TMAXT];                   // {start, k | cnt<<8}
__device__ int    g_ntiles[1];

// ============================================================================
// PTX helpers
// ============================================================================
__device__ __forceinline__ uint32_t smem_to_u32(const void* smem_ptr) {
    uint32_t addr;
    asm("{ .reg .u64 tmp; cvta.to.shared.u64 tmp, %1; cvt.u32.u64 %0, tmp; }"
        : "=r"(addr) : "l"(smem_ptr));
    return addr;
}
__device__ __forceinline__ void cp_async16(uint32_t dst, const void* src) {
    asm volatile("cp.async.cg.shared.global [%0], [%1], 16;"
                 :: "r"(dst), "l"(src));
}
__device__ __forceinline__ void cp_commit() {
    asm volatile("cp.async.commit_group;");
}
template <int N>
__device__ __forceinline__ void cp_wait() {
    asm volatile("cp.async.wait_group %0;" :: "n"(N));
}
__device__ __forceinline__ void ldmatrix_x4(uint32_t* a, uint32_t addr) {
    asm volatile("ldmatrix.sync.aligned.m8n8.x4.shared.b16 {%0,%1,%2,%3}, [%4];"
                 : "=r"(a[0]), "=r"(a[1]), "=r"(a[2]), "=r"(a[3]) : "r"(addr));
}
__device__ __forceinline__ void mma16816(float* c, const uint32_t* a,
                                         const uint32_t* b) {
    asm volatile(
        "mma.sync.aligned.m16n8k16.row.col.f32.f16.f16.f32 "
        "{%0,%1,%2,%3}, {%4,%5,%6,%7}, {%8,%9}, {%0,%1,%2,%3};"
        : "+f"(c[0]), "+f"(c[1]), "+f"(c[2]), "+f"(c[3])
        : "r"(a[0]), "r"(a[1]), "r"(a[2]), "r"(a[3]), "r"(b[0]), "r"(b[1]));
}

// ============================================================================
// Pair-list construction (unchanged, known-good)
// ============================================================================
__global__ void __launch_bounds__(NBLK)
k_fill(const int* __restrict__ nidx, int* __restrict__ kcnt,
       int* __restrict__ inlist, int* __restrict__ rowpairs,
       int* __restrict__ rcnt) {
    __shared__ int wpre[KOFF][NWARP];
    __shared__ int kbase[KOFF];
    const int t = threadIdx.x, b = blockIdx.x;
    const int w = t >> 5, lane = t & 31;
    const int row = b * NBLK + t;
    const int* ip = nidx + (size_t)row * KOFF;
    unsigned m = 0;
    #pragma unroll
    for (int k = 0; k < KOFF; k++)
        m |= (unsigned)(ip[k] >= 0) << k;
    #pragma unroll
    for (int k = 0; k < KOFF; k++) {
        unsigned bal = __ballot_sync(0xFFFFFFFFu, (m >> k) & 1u);
        if (lane == 0) wpre[k][w] = __popc(bal);
    }
    __syncthreads();
    if (t < KOFF) {
        int run = 0;
        #pragma unroll
        for (int g = 0; g < NWARP; g++) {
            int c = wpre[t][g];
            wpre[t][g] = run;
            run += c;
        }
        kbase[t] = atomicAdd(&kcnt[t], run);
    }
    __syncthreads();
    int slot = 0;
    const unsigned lt = (lane == 0) ? 0u : (0xFFFFFFFFu >> (32 - lane));
    #pragma unroll
    for (int k = 0; k < KOFF; k++) {
        const unsigned v = (m >> k) & 1u;
        const unsigned bal = __ballot_sync(0xFFFFFFFFu, v);
        if (v) {
            int p = k * NVOX + kbase[k] + wpre[k][w] + __popc(bal & lt);
            inlist[p] = ip[k];
            rowpairs[(size_t)row * KOFF + slot] = p;
            slot++;
        }
    }
    rcnt[row] = slot;
}

__global__ void k_tiles(const int* __restrict__ kcnt, int2* __restrict__ tiles,
                        int* __restrict__ ntiles) {
    __shared__ int tc[KOFF], tb[KOFF];
    const int t = threadIdx.x;
    if (t < KOFF) tc[t] = (kcnt[t] + TILE - 1) / TILE;
    __syncthreads();
    if (t == 0) {
        int run = 0;
        for (int k = 0; k < KOFF; k++) { tb[k] = run; run += tc[k]; }
        *ntiles = run;
    }
    __syncthreads();
    if (t < KOFF) {
        const int cnt = kcnt[t];
        for (int j = 0; j < tc[t]; j++)
            tiles[tb[t] + j] = make_int2(t * NVOX + j * TILE,
                                         t | (min(TILE, cnt - j * TILE) << 8));
    }
}

// ============================================================================
// Phase A: depth-2 cp.async pipeline, TILE=128, contiguous per-CTA ranges,
// B staged to SMEM on k-change only and held in REGISTERS across same-k tiles.
// COUT=64: warp-pair n-split (pair p: rows 32p..32p+31; warp0 n[0,32),
//          warp1 n[32,64)) -> bfrag 32 regs + acc 32 regs -> 3 CTAs/SM.
// COUT=16: 8 warps x m16 (unsplit).
// ============================================================================
template <int COUT>
__global__ void __launch_bounds__(256, 3)
phaseA(const __half* __restrict__ feat, const __half* __restrict__ Wf,
       const int* __restrict__ inlist, const int2* __restrict__ tiles,
       const int* __restrict__ ntiles_p, __half* __restrict__ partial)
{
    constexpr bool SPLIT   = (COUT == 64);
    constexpr int NO       = COUT / 8;            // total n8 tiles
    constexpr int NOW      = SPLIT ? NO / 2 : NO; // n8 tiles per warp
    constexpr int MT       = SPLIT ? 2 : 1;       // m16 tiles per warp
    constexpr int B_BYTES  = COUT * 128;
    constexpr int A_BYTES  = TILE * 128;          // 16384
    extern __shared__ char smem[];
    const uint32_t smem_base = smem_to_u32(smem);
    const uint32_t bRegion   = smem_base + 2 * A_BYTES;
    const int tid  = threadIdx.x;
    const int wid  = tid >> 5;
    const int lane = tid & 31;
    const int nt   = *ntiles_p;
    const int m0   = SPLIT ? (wid >> 1) * 32 : wid * 16;
    const int nb0  = SPLIT ? (wid & 1) * NOW : 0;   // warp's first n8 tile
    const int G    = gridDim.x;

    // contiguous balanced range [t0, te)
    const int per = nt / G;
    const int rem = nt - per * G;
    const int t0  = blockIdx.x * per + min(blockIdx.x, rem);
    const int te  = t0 + per + (blockIdx.x < rem ? 1 : 0);

    int kprev = -1;
    int bsel  = 0;
    int bslot[2];

    auto stage = [&](int t, int abuf) {
        if (t < te) {
            const int2 d = tiles[t];
            const int start = d.x;
            const int k     = d.y & 31;
            const int cnt   = d.y >> 8;
            const bool newk = (k != kprev);
            kprev = k;
            if (newk) bsel ^= 1;
            bslot[abuf] = bsel;
            if (newk) {
                const char* bs = (const char*)Wf + (size_t)k * B_BYTES;
                const uint32_t bd = bRegion + bsel * B_BYTES;
                #pragma unroll
                for (int j = tid; j < B_BYTES / 16; j += 256)
                    cp_async16(bd + j * 16, bs + (size_t)j * 16);
            }
            const uint32_t base = smem_base + abuf * A_BYTES;
            const int ch = tid & 7;
            #pragma unroll
            for (int c = 0; c < 4; c++) {
                const int r = c * 32 + (tid >> 3);
                if (r < cnt) {
                    int in_row = inlist[start + r];
                    const char* src = (const char*)(feat + (size_t)in_row * 64)
                                      + ch * 16;
                    cp_async16(base + r * 128 + ((uint32_t)(ch * 16)
                               ^ ((uint32_t)(r & 7) * 16)), src);
                }
            }
        }
        cp_commit();
    };

    stage(t0, 0);

    uint32_t bfrag[4][NOW][2];    // this warp's B fragments, held across k
    int kreg = -1;

    int si = 0;
    for (int t = t0; t < te; t++, si++) {
        stage(t + 1, (si + 1) & 1);
        cp_wait<1>();
        __syncthreads();

        const int2 d = tiles[t];
        const int start = d.x;
        const int cnt   = d.y >> 8;
        const int kt    = d.y & 31;
        const int abuf  = si & 1;
        const uint32_t aBase = smem_base + abuf * A_BYTES;

        if (kt != kreg) {             // reload B fragments (once per k)
            kreg = kt;
            const uint32_t bBase = bRegion + bslot[abuf] * B_BYTES;
            #pragma unroll
            for (int ko = 0; ko < 4; ko++)
                #pragma unroll
                for (int no = 0; no < NOW; no++)
                    asm volatile("ld.shared.v2.b32 {%0,%1}, [%2];"
                                 : "=r"(bfrag[ko][no][0]),
                                   "=r"(bfrag[ko][no][1])
                                 : "r"(bBase +
                                       ((ko * NO + nb0 + no) * 32 + lane) * 8));
        }

        float acc[MT][NOW][4];
        #pragma unroll
        for (int mt = 0; mt < MT; mt++)
            #pragma unroll
            for (int no = 0; no < NOW; no++)
                #pragma unroll
                for (int r = 0; r < 4; r++)
                    acc[mt][no][r] = 0.f;

        #pragma unroll
        for (int ko = 0; ko < 4; ko++) {
            uint32_t afrag[MT][4];
            const int ch = ko * 2 + (lane >> 4);
            #pragma unroll
            for (int mt = 0; mt < MT; mt++) {
                const int r = m0 + mt * 16 + (lane & 15);
                ldmatrix_x4(afrag[mt],
                    aBase + r * 128 + (((uint32_t)ch ^ (uint32_t)(r & 7)) * 16));
            }
            #pragma unroll
            for (int mt = 0; mt < MT; mt++)
                #pragma unroll
                for (int no = 0; no < NOW; no++)
                    mma16816(acc[mt][no], afrag[mt], bfrag[ko][no]);
        }

        // ---- direct global stores, tail-guarded ----
        #pragma unroll
        for (int mt = 0; mt < MT; mt++) {
            const int lr = m0 + mt * 16 + (lane >> 2);
            #pragma unroll
            for (int no = 0; no < NOW; no++) {
                const int c0 = (nb0 + no) * 8 + (lane & 3) * 2;
                if (lr < cnt)
                    *(__half2*)(partial + (size_t)(start + lr) * COUT + c0) =
                        __floats2half2_rn(acc[mt][no][0], acc[mt][no][1]);
                if (lr + 8 < cnt)
                    *(__half2*)(partial + (size_t)(start + lr + 8) * COUT + c0) =
                        __floats2half2_rn(acc[mt][no][2], acc[mt][no][3]);
            }
        }
        __syncthreads();
    }
}

// ============================================================================
// Phase B (MLP-pipelined, known-good):
//   out[row,:] = act( sum_j partial[rp[j],:] + bias )
// ============================================================================
template <int COUT, bool RELU, typename OUT_T>
__global__ void __launch_bounds__(256)
phaseB(const __half* __restrict__ partial, const int* __restrict__ rowpairs,
       const int* __restrict__ rcnt, const float* __restrict__ bias,
       OUT_T* __restrict__ out)
{
    constexpr int TPR = COUT / 16;
    constexpr int UNR = 6;
    const int gid = blockIdx.x * 256 + threadIdx.x;
    const int row = gid / TPR;
    const int q   = gid % TPR;

    float acc[16];
    #pragma unroll
    for (int i = 0; i < 16; i++) acc[i] = bias[q * 16 + i];

    const int cnt = rcnt[row];
    const int* rp = rowpairs + (size_t)row * KOFF;

    int pj[UNR];
    #pragma unroll
    for (int j = 0; j < UNR; j++)
        pj[j] = rp[j < cnt ? j : 0];

    #pragma unroll
    for (int j = 0; j < UNR; j++) {
        const uint4* pr = (const uint4*)(partial + (size_t)pj[j] * COUT + q * 16);
        uint4 u0 = pr[0], u1 = pr[1];
        if (j < cnt) {
            const uint32_t* u = (const uint32_t*)&u0;
            #pragma unroll
            for (int h = 0; h < 4; h++) {
                float2 f = __half22float2(*(const __half2*)&u[h]);
                acc[h * 2]     += f.x;
                acc[h * 2 + 1] += f.y;
            }
            const uint32_t* v = (const uint32_t*)&u1;
            #pragma unroll
            for (int h = 0; h < 4; h++) {
                float2 f = __half22float2(*(const __half2*)&v[h]);
                acc[8 + h * 2]     += f.x;
                acc[8 + h * 2 + 1] += f.y;
            }
        }
    }
    for (int j = UNR; j < cnt; j++) {       // rare tail (cnt > 6)
        const int p = rp[j];
        const uint4* pr = (const uint4*)(partial + (size_t)p * COUT + q * 16);
        uint4 u0 = pr[0], u1 = pr[1];
        const uint32_t* u = (const uint32_t*)&u0;
        #pragma unroll
        for (int h = 0; h < 4; h++) {
            float2 f = __half22float2(*(const __half2*)&u[h]);
            acc[h * 2]     += f.x;
            acc[h * 2 + 1] += f.y;
        }
        const uint32_t* v = (const uint32_t*)&u1;
        #pragma unroll
        for (int h = 0; h < 4; h++) {
            float2 f = __half22float2(*(const __half2*)&v[h]);
            acc[8 + h * 2]     += f.x;
            acc[8 + h * 2 + 1] += f.y;
        }
    }

    if (RELU) {
        #pragma unroll
        for (int i = 0; i < 16; i++) acc[i] = fmaxf(acc[i], 0.f);
    }
    if constexpr (sizeof(OUT_T) == 2) {
        __half2 hs[8];
        #pragma unroll
        for (int i = 0; i < 8; i++)
            hs[i] = __floats2half2_rn(acc[2 * i], acc[2 * i + 1]);
        uint4* dst = (uint4*)((__half*)out + (size_t)row * COUT + q * 16);
        dst[0] = *(uint4*)&hs[0];
        dst[1] = *(uint4*)&hs[4];
    } else {
        float4* dst = (float4*)((float*)out + (size_t)row * COUT + q * 16);
        #pragma unroll
        for (int i = 0; i < 4; i++)
            dst[i] = make_float4(acc[4 * i], acc[4 * i + 1],
                                 acc[4 * i + 2], acc[4 * i + 3]);
    }
}

// ============================================================================
// Fused prologue: x -> fp16, and W1/W2/W3 -> mma B-fragment order
// ============================================================================
__device__ __forceinline__ void prep_b_elem(const float* __restrict__ W,
                                            __half* __restrict__ Bf,
                                            int Cout, int i) {
    int NOv  = Cout / 8;
    int lane = i & 31;
    int g    = i >> 5;
    int no   = g % NOv;
    int ko   = (g / NOv) % 4;
    int k    = g / (NOv * 4);
    int n    = no * 8 + (lane >> 2);
    int kk0  = ko * 16 + (lane & 3) * 2;
    const float* Wk = W + (size_t)k * 64 * Cout;
    __half h0 = __float2half_rn(Wk[(kk0 + 0) * Cout + n]);
    __half h1 = __float2half_rn(Wk[(kk0 + 1) * Cout + n]);
    __half h2 = __float2half_rn(Wk[(kk0 + 8) * Cout + n]);
    __half h3 = __float2half_rn(Wk[(kk0 + 9) * Cout + n]);
    uint2 v;
    v.x = (uint32_t)__half_as_ushort(h0) | ((uint32_t)__half_as_ushort(h1) << 16);
    v.y = (uint32_t)__half_as_ushort(h2) | ((uint32_t)__half_as_ushort(h3) << 16);
    ((uint2*)Bf)[i] = v;
}

static constexpr int PREP_NP  = NVOX * CIN / 2;
static constexpr int PREP_T12 = KOFF * 4 * 8 * 32;
static constexpr int PREP_T3  = KOFF * 4 * 2 * 32;
static constexpr int PREP_TOT = PREP_NP + 2 * PREP_T12 + PREP_T3;

__global__ void k_prep(const float* __restrict__ x, __half* __restrict__ xh,
                       const float* __restrict__ W1, __half* __restrict__ w1f,
                       const float* __restrict__ W2, __half* __restrict__ w2f,
                       const float* __restrict__ W3, __half* __restrict__ w3f) {
    int i = blockIdx.x * blockDim.x + threadIdx.x;
    if (i < PREP_NP) {
        float2 v = ((const float2*)x)[i];
        ((__half2*)xh)[i] = __floats2half2_rn(v.x, v.y);
    } else if (i < PREP_NP + PREP_T12) {
        prep_b_elem(W1, w1f, 64, i - PREP_NP);
    } else if (i < PREP_NP + 2 * PREP_T12) {
        prep_b_elem(W2, w2f, 64, i - PREP_NP - PREP_T12);
    } else if (i < PREP_TOT) {
        prep_b_elem(W3, w3f, 16, i - PREP_NP - 2 * PREP_T12);
    }
}

// ============================================================================
// kernel_launch
// ============================================================================
extern "C" void kernel_launch(void* const* d_in, const int* in_sizes, int n_in,
                              void* d_out, int out_size) {
    const float* x    = (const float*)d_in[0];
    const int*   nidx = (const int*)  d_in[1];
    const float* W1   = (const float*)d_in[2];
    const float* b1   = (const float*)d_in[3];
    const float* W2   = (const float*)d_in[4];
    const float* b2   = (const float*)d_in[5];
    const float* W3   = (const float*)d_in[6];
    const float* b3   = (const float*)d_in[7];

    __half *xh, *h1, *h2, *w1f, *w2f, *w3f, *part;
    int *inl, *rp, *rc, *kc, *ntl;
    int2* tl;
    cudaGetSymbolAddress((void**)&xh,   g_xh);
    cudaGetSymbolAddress((void**)&h1,   g_h1);
    cudaGetSymbolAddress((void**)&h2,   g_h2);
    cudaGetSymbolAddress((void**)&w1f,  g_W1f);
    cudaGetSymbolAddress((void**)&w2f,  g_W2f);
    cudaGetSymbolAddress((void**)&w3f,  g_W3f);
    cudaGetSymbolAddress((void**)&part, g_partial);
    cudaGetSymbolAddress((void**)&inl,  g_inlist);
    cudaGetSymbolAddress((void**)&rp,   g_rowpairs);
    cudaGetSymbolAddress((void**)&rc,   g_rcnt);
    cudaGetSymbolAddress((void**)&kc,   g_kcnt);
    cudaGetSymbolAddress((void**)&tl,   g_tiles);
    cudaGetSymbolAddress((void**)&ntl,  g_ntiles);

    // ---- fork: pair-list branch (reads only nidx) runs parallel to k_prep ----
    cudaStream_t s1;
    cudaStreamCreateWithFlags(&s1, cudaStreamNonBlocking);
    cudaEvent_t e0, e1;
    cudaEventCreateWithFlags(&e0, cudaEventDisableTiming);
    cudaEventCreateWithFlags(&e1, cudaEventDisableTiming);

    cudaEventRecord(e0, 0);
    cudaStreamWaitEvent(s1, e0, 0);

    k_prep<<<(PREP_TOT + 255) / 256, 256>>>(x, xh, W1, w1f, W2, w2f, W3, w3f);

    cudaMemsetAsync(kc, 0, KOFF * sizeof(int), s1);
    k_fill<<<NROWB, NBLK, 0, s1>>>(nidx, kc, inl, rp, rc);
    k_tiles<<<1, 32, 0, s1>>>(kc, tl, ntl);

    cudaEventRecord(e1, s1);
    cudaStreamWaitEvent(0, e1, 0);

    constexpr int SZA64 = 2 * TILE * 128 + 2 * 64 * 128;  // 49152
    constexpr int SZA16 = 2 * TILE * 128 + 2 * 16 * 128;  // 36864
    constexpr int GA = 444;                               // 3 CTAs/SM
    cudaFuncSetAttribute((const void*)phaseA<64>,
                         cudaFuncAttributeMaxDynamicSharedMemorySize, SZA64);
    cudaFuncSetAttribute((const void*)phaseA<16>,
                         cudaFuncAttributeMaxDynamicSharedMemorySize, SZA16);

    // layer 1
    phaseA<64><<<GA, 256, SZA64>>>(xh, w1f, inl, tl, ntl, part);
    phaseB<64, true, __half><<<NVOX * 4 / 256, 256>>>(part, rp, rc, b1, h1);
    // layer 2
    phaseA<64><<<GA, 256, SZA64>>>(h1, w2f, inl, tl, ntl, part);
    phaseB<64, true, __half><<<NVOX * 4 / 256, 256>>>(part, rp, rc, b2, h2);
    // layer 3
    phaseA<16><<<GA, 256, SZA16>>>(h2, w3f, inl, tl, ntl, part);
    phaseB<16, false, float><<<NVOX / 256, 256>>>(part, rp, rc, b3,
                                                  (float*)d_out);

    cudaEventDestroy(e0);
    cudaEventDestroy(e1);
    cudaStreamDestroy(s1);
}